// round 12
// baseline (speedup 1.0000x reference)
#include <cuda_runtime.h>
#include <cuda_fp16.h>
#include <cstdint>

#define MAXN 131072
#define EPB 512          // edges per block (256 threads x 2)
#define NPB 128          // nodes per precompute block (2 threads per node)

// Packed tables: one uint4 (16B) per node per table.
// 12-bit unsigned q values (bias 2048) + fp16 row scale.
__device__ uint4 g_Y[MAXN];
__device__ uint4 g_Z[MAXN];

// fused-kernel barrier state (reset by the last-finishing block every launch)
__device__ int g_start_cnt = 0;
__device__ int g_done_cnt  = 0;

// ---------------- helpers ----------------
__device__ __forceinline__ unsigned int tanh_h2(float lo, float hi) {
    __half2 h = __floats2half2_rn(lo, hi);
    unsigned int u;
    { union { __half2 h; unsigned int u; } cvt; cvt.h = h; u = cvt.u; }
    asm("tanh.approx.f16x2 %0, %0;" : "+r"(u));
    return u;
}

__device__ __forceinline__ uint4 pack_row(const float* v) {
    float mx = fabsf(v[0]);
#pragma unroll
    for (int o = 1; o < 9; o++) mx = fmaxf(mx, fabsf(v[o]));
    // quantize against the STORED (fp16-rounded) scale: no systematic scale error
    __half hs = __float2half_rn(fmaxf(mx, 1e-20f) * (1.0f / 2047.0f));
    float inv = __fdividef(1.0f, __half2float(hs));

    unsigned int q[9];
#pragma unroll
    for (int o = 0; o < 9; o++) {
        int qi = __float2int_rn(v[o] * inv);
        qi = max(-2047, min(2047, qi));
        q[o] = (unsigned int)(qi + 2048);
    }
    uint4 w;
    w.x = q[0] | (q[1] << 12) | (q[2] << 24);
    w.y = (q[2] >> 8) | (q[3] << 4) | (q[4] << 16) | (q[5] << 28);
    w.z = (q[5] >> 4) | (q[6] << 8) | (q[7] << 20);
    w.w = q[8] | ((unsigned int)__half_as_ushort(hs) << 16);
    return w;
}

__device__ __forceinline__ void unpack_row(uint4 w, float q[9], float& s) {
    q[0] = (float)( w.x        & 0xFFFu);
    q[1] = (float)((w.x >> 12) & 0xFFFu);
    q[2] = (float)(((w.x >> 24) | (w.y << 8)) & 0xFFFu);
    q[3] = (float)((w.y >> 4)  & 0xFFFu);
    q[4] = (float)((w.y >> 16) & 0xFFFu);
    q[5] = (float)(((w.y >> 28) | (w.z << 4)) & 0xFFFu);
    q[6] = (float)((w.z >> 8)  & 0xFFFu);
    q[7] = (float)( w.z >> 20);
    q[8] = (float)( w.w        & 0xFFFu);
    s = __half2float(__ushort_as_half((unsigned short)(w.w >> 16)));
}

__device__ __forceinline__ void decode_edge_sum(uint4 yw, uint4 zw, float* a) {
    float qy[9], qz[9], sy, sz;
    unpack_row(yw, qy, sy);
    unpack_row(zw, qz, sz);
    float c = -2048.0f * (sy + sz);
#pragma unroll
    for (int o = 0; o < 9; o++)
        a[o] = fmaf(sy, qy[o], fmaf(sz, qz[o], c));
}

// ---------------------------------------------------------------------------
// Fused kernel, register-balanced:
//   __launch_bounds__(256,6): 40-reg cap, 6 blocks/SM = 48 warps — the exact
//   configuration where the R7 edge kernel (38 regs) ran its 23.5us floor.
//   phase 1 (bid < preBlocks): 2 threads per node — even thread computes and
//     packs Y only, odd thread Z only (9 accumulators each, ~31 regs). x rows
//     cooperatively staged in smem (coalesced LDG.128, stride-36 pad).
//   barrier: flag release/acquire; ei prefetched before the wait.
//   phase 2 (all blocks): R7 edge gather/decode/tanh/store.
// Deadlock-free: preBlocks = ceil(N/128) = 782 <= 6*148 = 888 resident.
// ---------------------------------------------------------------------------
__global__ void __launch_bounds__(256, 6)
fused_kernel(const float* __restrict__ x,
             const int* __restrict__ ei,
             const int* __restrict__ nt,
             const float* __restrict__ W,
             float* __restrict__ out,
             int N, int E, int preBlocks) {
    __shared__ __align__(16) float sW[9 * 72];            // 2592 B
    __shared__ __align__(16) char sraw[NPB * 36 * 4];     // 18432 B (xs / ob)
    float* xs        = reinterpret_cast<float*>(sraw);
    unsigned int* ob = reinterpret_cast<unsigned int*>(sraw);

    const int bid = blockIdx.x;
    const int tid = threadIdx.x;

    // ---------------- phase 1: precompute (782 blocks, 128 nodes each) -----
    if (bid < preBlocks) {
        for (int i = tid; i < 9 * 72; i += 256) sW[i] = W[i];

        int base = bid * NPB;
        // cooperative coalesced stage of 128 x-rows (1024 float4, 4 per thread)
        const float4* xp = reinterpret_cast<const float4*>(x);
#pragma unroll
        for (int i = 0; i < 4; i++) {
            int lin = i * 256 + tid;          // 0..1023
            int nl  = lin >> 3;               // local node 0..127
            int cp  = lin & 7;                // float4 within row
            if (base + nl < N)
                *reinterpret_cast<float4*>(xs + nl * 36 + cp * 4) =
                    xp[(size_t)(base + nl) * 8 + cp];
        }
        __syncthreads();

        int nl  = tid >> 1;                   // local node
        int sel = tid & 1;                    // 0 -> Y, 1 -> Z
        int n   = base + nl;
        if (n < N) {
            int t = nt[n];                    // pair loads same addr (coalesced-ish)

            float acc[9];
#pragma unroll
            for (int o = 0; o < 9; o++) acc[o] = sW[o * 72 + 64 + sel * 4 + t];

            const float4* xrow = reinterpret_cast<const float4*>(xs + nl * 36);
#pragma unroll
            for (int i = 0; i < 8; i++) {
                float4 xv = xrow[i];          // broadcast within thread pair
#pragma unroll
                for (int o = 0; o < 9; o++) {
                    float4 wv = *reinterpret_cast<const float4*>(
                        sW + o * 72 + sel * 32 + i * 4);
                    acc[o] = fmaf(xv.x, wv.x, acc[o]);
                    acc[o] = fmaf(xv.y, wv.y, acc[o]);
                    acc[o] = fmaf(xv.z, wv.z, acc[o]);
                    acc[o] = fmaf(xv.w, wv.w, acc[o]);
                }
            }
            uint4 packed = pack_row(acc);
            if (sel == 0) g_Y[n] = packed;
            else          g_Z[n] = packed;
        }
        __threadfence();       // release table rows
        __syncthreads();       // done reading xs before ob reuse
        if (tid == 0) atomicAdd(&g_start_cnt, 1);
    }

    // ---------------- edge-index loads (before barrier wait) ----------------
    int pt = bid * 256 + tid;   // pair index
    int e0 = 2 * pt;
    bool v0 = (e0 < E), v1 = (e0 + 1 < E);

    int2 sp = make_int2(0, 0), dp = make_int2(0, 0);
    if (v1) {
        if ((E & 1) == 0) {
            sp = reinterpret_cast<const int2*>(ei)[pt];
            dp = reinterpret_cast<const int2*>(ei + E)[pt];
        } else {
            sp = make_int2(ei[e0], ei[e0 + 1]);
            dp = make_int2(ei[E + e0], ei[E + e0 + 1]);
        }
    } else if (v0) {
        sp.x = ei[e0];
        dp.x = ei[E + e0];
    }

    // ---------------- device-wide barrier ----------------
    if (tid == 0) {
        while (*(volatile int*)&g_start_cnt < preBlocks) __nanosleep(64);
        __threadfence();       // acquire
    }
    __syncthreads();

    // ---------------- phase 2: edges (R7 body) ----------------
    uint4 y0, y1, z0, z1;
    if (v1) {
        y0 = __ldg(&g_Y[sp.x]);
        z0 = __ldg(&g_Z[dp.x]);
        y1 = __ldg(&g_Y[sp.y]);
        z1 = __ldg(&g_Z[dp.y]);
    } else if (v0) {
        y0 = __ldg(&g_Y[sp.x]);
        z0 = __ldg(&g_Z[dp.x]);
        y1 = make_uint4(0, 0, 0, 0);
        z1 = make_uint4(0, 0, 0, 0);
    } else {
        y0 = y1 = z0 = z1 = make_uint4(0, 0, 0, 0);
    }

    float a[18];
    decode_edge_sum(y0, z0, a);
    decode_edge_sum(y1, z1, a + 9);

    unsigned int rh[9];
#pragma unroll
    for (int k = 0; k < 9; k++) rh[k] = tanh_h2(a[2 * k], a[2 * k + 1]);

#pragma unroll
    for (int k = 0; k < 9; k++) ob[tid * 9 + k] = rh[k];
    __syncthreads();

    // coalesced output: 2304 half2 per block -> float2 stores
    long long lim    = (long long)E * 9;              // total floats
    long long g2base = (long long)bid * 2304;         // half2 index base
#pragma unroll
    for (int it = 0; it < 9; it++) {
        int i = it * 256 + tid;                       // 0..2303
        long long g2 = g2base + i;
        long long f0 = 2 * g2;
        if (f0 + 1 < lim) {
            union { unsigned int u; __half2 h; } cvt; cvt.u = ob[i];
            reinterpret_cast<float2*>(out)[g2] = __half22float2(cvt.h);
        } else if (f0 < lim) {
            union { unsigned int u; __half2 h; } cvt; cvt.u = ob[i];
            out[f0] = __low2float(cvt.h);
        }
    }

    // ---------------- epilogue: reset counters for next replay ----------
    if (tid == 0) {
        int dcount = atomicAdd(&g_done_cnt, 1) + 1;
        if (dcount == (int)gridDim.x) {
            g_done_cnt  = 0;
            g_start_cnt = 0;
        }
    }
}

extern "C" void kernel_launch(void* const* d_in, const int* in_sizes, int n_in,
                              void* d_out, int out_size) {
    // metadata order: x [N,32] f32, edge_index [2,E] i32, node_types [N] i32, W [9,72] f32
    const float* x  = (const float*)d_in[0];
    const int*   ei = (const int*)d_in[1];
    const int*   nt = (const int*)d_in[2];
    const float* W  = (const float*)d_in[3];
    float* out = (float*)d_out;

    int N = in_sizes[2];
    int E = in_sizes[1] / 2;

    int preBlocks  = (N + NPB - 1) / NPB;      // 782
    int edgeBlocks = (E + EPB - 1) / EPB;      // 3125
    int grid = max(preBlocks, edgeBlocks);

    fused_kernel<<<grid, 256>>>(x, ei, nt, W, out, N, E, preBlocks);
}

// round 13
// speedup vs baseline: 1.2403x; 1.2403x over previous
#include <cuda_runtime.h>
#include <cuda_fp16.h>
#include <cstdint>

#define MAXN 131072
#define EPB 512          // edges per block (256 threads x 2)
#define NPB 128          // nodes per precompute block (2 threads per node)

// Packed tables: one uint4 (16B) per node per table.
// 12-bit unsigned q values (bias 2048) + fp16 row scale.
__device__ uint4 g_Y[MAXN];
__device__ uint4 g_Z[MAXN];

// ---------------- helpers ----------------
__device__ __forceinline__ unsigned int tanh_h2(float lo, float hi) {
    __half2 h = __floats2half2_rn(lo, hi);
    unsigned int u;
    { union { __half2 h; unsigned int u; } cvt; cvt.h = h; u = cvt.u; }
    asm("tanh.approx.f16x2 %0, %0;" : "+r"(u));
    return u;
}

__device__ __forceinline__ uint4 pack_row(const float* v) {
    float mx = fabsf(v[0]);
#pragma unroll
    for (int o = 1; o < 9; o++) mx = fmaxf(mx, fabsf(v[o]));
    // quantize against the STORED (fp16-rounded) scale: no systematic scale error
    __half hs = __float2half_rn(fmaxf(mx, 1e-20f) * (1.0f / 2047.0f));
    float inv = __fdividef(1.0f, __half2float(hs));

    unsigned int q[9];
#pragma unroll
    for (int o = 0; o < 9; o++) {
        int qi = __float2int_rn(v[o] * inv);
        qi = max(-2047, min(2047, qi));
        q[o] = (unsigned int)(qi + 2048);
    }
    uint4 w;
    w.x = q[0] | (q[1] << 12) | (q[2] << 24);
    w.y = (q[2] >> 8) | (q[3] << 4) | (q[4] << 16) | (q[5] << 28);
    w.z = (q[5] >> 4) | (q[6] << 8) | (q[7] << 20);
    w.w = q[8] | ((unsigned int)__half_as_ushort(hs) << 16);
    return w;
}

__device__ __forceinline__ void unpack_row(uint4 w, float q[9], float& s) {
    q[0] = (float)( w.x        & 0xFFFu);
    q[1] = (float)((w.x >> 12) & 0xFFFu);
    q[2] = (float)(((w.x >> 24) | (w.y << 8)) & 0xFFFu);
    q[3] = (float)((w.y >> 4)  & 0xFFFu);
    q[4] = (float)((w.y >> 16) & 0xFFFu);
    q[5] = (float)(((w.y >> 28) | (w.z << 4)) & 0xFFFu);
    q[6] = (float)((w.z >> 8)  & 0xFFFu);
    q[7] = (float)( w.z >> 20);
    q[8] = (float)( w.w        & 0xFFFu);
    s = __half2float(__ushort_as_half((unsigned short)(w.w >> 16)));
}

__device__ __forceinline__ void decode_edge_sum(uint4 yw, uint4 zw, float* a) {
    float qy[9], qz[9], sy, sz;
    unpack_row(yw, qy, sy);
    unpack_row(zw, qz, sz);
    float c = -2048.0f * (sy + sz);
#pragma unroll
    for (int o = 0; o < 9; o++)
        a[o] = fmaf(sy, qy[o], fmaf(sz, qz[o], c));
}

// ---------------------------------------------------------------------------
// Kernel 1: per-node precompute, 2 threads per node (even->Y, odd->Z).
// 782 blocks x 256 threads; x staged cooperatively (coalesced LDG.128,
// stride-36 smem rows -> conflict-free LDS.128 phases); W in smem (broadcast).
// Per-thread: 9 accumulators, 288 FMAs (~31 regs).
// ---------------------------------------------------------------------------
__global__ void __launch_bounds__(256)
node_precompute(const float* __restrict__ x,
                const int* __restrict__ node_types,
                const float* __restrict__ W,
                int N) {
    __shared__ __align__(16) float sW[9 * 72];          // 2592 B
    __shared__ __align__(16) float xs[NPB * 36];        // 18432 B

    const int tid = threadIdx.x;
    for (int i = tid; i < 9 * 72; i += 256) sW[i] = W[i];

    int base = blockIdx.x * NPB;
    // cooperative coalesced stage of 128 x-rows (1024 float4, 4 per thread)
    const float4* xp = reinterpret_cast<const float4*>(x);
#pragma unroll
    for (int i = 0; i < 4; i++) {
        int lin = i * 256 + tid;          // 0..1023
        int nl  = lin >> 3;               // local node 0..127
        int cp  = lin & 7;                // float4 within row
        if (base + nl < N)
            *reinterpret_cast<float4*>(xs + nl * 36 + cp * 4) =
                xp[(size_t)(base + nl) * 8 + cp];
    }
    __syncthreads();

    int nl  = tid >> 1;                   // local node
    int sel = tid & 1;                    // 0 -> Y, 1 -> Z
    int n   = base + nl;
    if (n >= N) return;

    int t = node_types[n];

    float acc[9];
#pragma unroll
    for (int o = 0; o < 9; o++) acc[o] = sW[o * 72 + 64 + sel * 4 + t];

    const float4* xrow = reinterpret_cast<const float4*>(xs + nl * 36);
#pragma unroll
    for (int i = 0; i < 8; i++) {
        float4 xv = xrow[i];              // pair-shared address
#pragma unroll
        for (int o = 0; o < 9; o++) {
            float4 wv = *reinterpret_cast<const float4*>(
                sW + o * 72 + sel * 32 + i * 4);
            acc[o] = fmaf(xv.x, wv.x, acc[o]);
            acc[o] = fmaf(xv.y, wv.y, acc[o]);
            acc[o] = fmaf(xv.z, wv.z, acc[o]);
            acc[o] = fmaf(xv.w, wv.w, acc[o]);
        }
    }

    uint4 packed = pack_row(acc);
    if (sel == 0) g_Y[n] = packed;
    else          g_Z[n] = packed;
}

// ---------------------------------------------------------------------------
// Kernel 2 (R7, unchanged): 2 edges/thread; 4 scattered LDG.128 up front;
// SIMD tanh; half2 smem staging; coalesced float2 stores.
// ---------------------------------------------------------------------------
__global__ void __launch_bounds__(256)
edge_kernel(const int* __restrict__ ei,
            float* __restrict__ out,
            int E) {
    __shared__ unsigned int sbuf[EPB * 9 / 2];   // 2304 half2 = 9216 B

    int t  = blockIdx.x * 256 + threadIdx.x;   // pair index
    int e0 = 2 * t;

    uint4 y0, y1, z0, z1;
    bool v0 = (e0 < E), v1 = (e0 + 1 < E);

    if (v1) {
        int2 sp, dp;
        if ((E & 1) == 0) {
            sp = reinterpret_cast<const int2*>(ei)[t];
            dp = reinterpret_cast<const int2*>(ei + E)[t];
        } else {
            sp = make_int2(ei[e0], ei[e0 + 1]);
            dp = make_int2(ei[E + e0], ei[E + e0 + 1]);
        }
        y0 = __ldg(&g_Y[sp.x]);
        z0 = __ldg(&g_Z[dp.x]);
        y1 = __ldg(&g_Y[sp.y]);
        z1 = __ldg(&g_Z[dp.y]);
    } else if (v0) {
        int s0 = ei[e0], d0 = ei[E + e0];
        y0 = __ldg(&g_Y[s0]);
        z0 = __ldg(&g_Z[d0]);
        y1 = make_uint4(0, 0, 0, 0);
        z1 = make_uint4(0, 0, 0, 0);
    } else {
        y0 = y1 = z0 = z1 = make_uint4(0, 0, 0, 0);
    }

    float a[18];
    decode_edge_sum(y0, z0, a);
    decode_edge_sum(y1, z1, a + 9);

#pragma unroll
    for (int k = 0; k < 9; k++)
        sbuf[threadIdx.x * 9 + k] = tanh_h2(a[2 * k], a[2 * k + 1]);
    __syncthreads();

    // coalesced output: 2304 half2 per block -> float2 stores
    long long lim    = (long long)E * 9;               // total floats
    long long g2base = (long long)blockIdx.x * 2304;   // half2 index base
#pragma unroll
    for (int it = 0; it < 9; it++) {
        int i = it * 256 + threadIdx.x;                // 0..2303
        long long g2 = g2base + i;
        long long f0 = 2 * g2;
        if (f0 + 1 < lim) {
            union { unsigned int u; __half2 h; } cvt; cvt.u = sbuf[i];
            reinterpret_cast<float2*>(out)[g2] = __half22float2(cvt.h);
        } else if (f0 < lim) {
            union { unsigned int u; __half2 h; } cvt; cvt.u = sbuf[i];
            out[f0] = __low2float(cvt.h);
        }
    }
}

extern "C" void kernel_launch(void* const* d_in, const int* in_sizes, int n_in,
                              void* d_out, int out_size) {
    // metadata order: x [N,32] f32, edge_index [2,E] i32, node_types [N] i32, W [9,72] f32
    const float* x  = (const float*)d_in[0];
    const int*   ei = (const int*)d_in[1];
    const int*   nt = (const int*)d_in[2];
    const float* W  = (const float*)d_in[3];
    float* out = (float*)d_out;

    int N = in_sizes[2];
    int E = in_sizes[1] / 2;

    node_precompute<<<(N + NPB - 1) / NPB, 256>>>(x, nt, W, N);
    edge_kernel<<<(E + EPB - 1) / EPB, 256>>>(ei, out, E);
}

// round 14
// speedup vs baseline: 1.2761x; 1.0289x over previous
#include <cuda_runtime.h>
#include <cuda_fp16.h>
#include <cstdint>

#define MAXN 131072
#define EPB 512   // edges per block (256 threads x 2)

// Packed tables: one uint4 (16B) per node per table.
// 12-bit unsigned q values (bias 2048) + fp16 row scale.
__device__ uint4 g_Y[MAXN];
__device__ uint4 g_Z[MAXN];

// ---------------- helpers ----------------
__device__ __forceinline__ unsigned int tanh_h2(float lo, float hi) {
    __half2 h = __floats2half2_rn(lo, hi);
    unsigned int u;
    { union { __half2 h; unsigned int u; } cvt; cvt.h = h; u = cvt.u; }
    asm("tanh.approx.f16x2 %0, %0;" : "+r"(u));
    return u;
}

__device__ __forceinline__ uint4 pack_row(const float* v) {
    float mx = fabsf(v[0]);
#pragma unroll
    for (int o = 1; o < 9; o++) mx = fmaxf(mx, fabsf(v[o]));
    // quantize against the STORED (fp16-rounded) scale: no systematic scale error
    __half hs = __float2half_rn(fmaxf(mx, 1e-20f) * (1.0f / 2047.0f));
    float inv = __fdividef(1.0f, __half2float(hs));

    unsigned int q[9];
#pragma unroll
    for (int o = 0; o < 9; o++) {
        int qi = __float2int_rn(v[o] * inv);
        qi = max(-2047, min(2047, qi));
        q[o] = (unsigned int)(qi + 2048);
    }
    uint4 w;
    w.x = q[0] | (q[1] << 12) | (q[2] << 24);
    w.y = (q[2] >> 8) | (q[3] << 4) | (q[4] << 16) | (q[5] << 28);
    w.z = (q[5] >> 4) | (q[6] << 8) | (q[7] << 20);
    w.w = q[8] | ((unsigned int)__half_as_ushort(hs) << 16);
    return w;
}

__device__ __forceinline__ void unpack_row(uint4 w, float q[9], float& s) {
    q[0] = (float)( w.x        & 0xFFFu);
    q[1] = (float)((w.x >> 12) & 0xFFFu);
    q[2] = (float)(((w.x >> 24) | (w.y << 8)) & 0xFFFu);
    q[3] = (float)((w.y >> 4)  & 0xFFFu);
    q[4] = (float)((w.y >> 16) & 0xFFFu);
    q[5] = (float)(((w.y >> 28) | (w.z << 4)) & 0xFFFu);
    q[6] = (float)((w.z >> 8)  & 0xFFFu);
    q[7] = (float)( w.z >> 20);
    q[8] = (float)( w.w        & 0xFFFu);
    s = __half2float(__ushort_as_half((unsigned short)(w.w >> 16)));
}

__device__ __forceinline__ void decode_edge_sum(uint4 yw, uint4 zw, float* a) {
    float qy[9], qz[9], sy, sz;
    unpack_row(yw, qy, sy);
    unpack_row(zw, qz, sz);
    float c = -2048.0f * (sy + sz);
#pragma unroll
    for (int o = 0; o < 9; o++)
        a[o] = fmaf(sy, qy[o], fmaf(sz, qz[o], c));
}

// ---------------------------------------------------------------------------
// Kernel 1 (R7 precompute, unchanged except the PDL trigger at block start):
// per-node Y/Z + 12-bit quantization; x staged via coalesced LDG.128.
// ---------------------------------------------------------------------------
__global__ void __launch_bounds__(256)
node_precompute(const float* __restrict__ x,
                const int* __restrict__ node_types,
                const float* __restrict__ W,
                int N) {
    // allow the dependent edge kernel to start launching now; its
    // griddepcontrol.wait still blocks until this grid's stores are visible.
    asm volatile("griddepcontrol.launch_dependents;" ::: "memory");

    __shared__ __align__(16) float sW[9 * 72];
    __shared__ __align__(16) float xs[256 * 36];

    for (int i = threadIdx.x; i < 9 * 72; i += blockDim.x) sW[i] = W[i];

    int base = blockIdx.x * 256;
    const float4* xp = reinterpret_cast<const float4*>(x);
#pragma unroll
    for (int i = 0; i < 8; i++) {
        int lin = i * 256 + threadIdx.x;
        int nl  = lin >> 3;
        int cp  = lin & 7;
        if (base + nl < N)
            *reinterpret_cast<float4*>(xs + nl * 36 + cp * 4) =
                xp[(size_t)(base + nl) * 8 + cp];
    }
    __syncthreads();

    int n = base + threadIdx.x;
    if (n >= N) return;

    float4 xr[8];
    const float4* myrow = reinterpret_cast<const float4*>(xs + threadIdx.x * 36);
#pragma unroll
    for (int i = 0; i < 8; i++) xr[i] = myrow[i];

    int t = node_types[n];

    float yv[9], zv[9];
#pragma unroll
    for (int o = 0; o < 9; o++) {
        const float4* w4 = reinterpret_cast<const float4*>(sW + o * 72);
        float accY = sW[o * 72 + 64 + t];
        float accZ = sW[o * 72 + 68 + t];
#pragma unroll
        for (int i = 0; i < 8; i++) {
            float4 wa = w4[i];
            float4 wb = w4[8 + i];
            accY = fmaf(xr[i].x, wa.x, accY);
            accY = fmaf(xr[i].y, wa.y, accY);
            accY = fmaf(xr[i].z, wa.z, accY);
            accY = fmaf(xr[i].w, wa.w, accY);
            accZ = fmaf(xr[i].x, wb.x, accZ);
            accZ = fmaf(xr[i].y, wb.y, accZ);
            accZ = fmaf(xr[i].z, wb.z, accZ);
            accZ = fmaf(xr[i].w, wb.w, accZ);
        }
        yv[o] = accY;
        zv[o] = accZ;
    }

    g_Y[n] = pack_row(yv);
    g_Z[n] = pack_row(zv);
}

// ---------------------------------------------------------------------------
// Kernel 2 (R7 body + PDL): ei loads BEFORE griddepcontrol.wait so the index
// traffic overlaps the precompute grid; gathers after the wait.
// ---------------------------------------------------------------------------
__global__ void __launch_bounds__(256)
edge_kernel(const int* __restrict__ ei,
            float* __restrict__ out,
            int E) {
    __shared__ unsigned int sbuf[EPB * 9 / 2];   // 2304 half2 = 9216 B

    int t  = blockIdx.x * 256 + threadIdx.x;   // pair index
    int e0 = 2 * t;
    bool v0 = (e0 < E), v1 = (e0 + 1 < E);

    // ---- prologue: table-independent index loads ----
    int2 sp = make_int2(0, 0), dp = make_int2(0, 0);
    if (v1) {
        if ((E & 1) == 0) {
            sp = reinterpret_cast<const int2*>(ei)[t];
            dp = reinterpret_cast<const int2*>(ei + E)[t];
        } else {
            sp = make_int2(ei[e0], ei[e0 + 1]);
            dp = make_int2(ei[E + e0], ei[E + e0 + 1]);
        }
    } else if (v0) {
        sp.x = ei[e0];
        dp.x = ei[E + e0];
    }

    // ---- wait for the precompute grid's memory to be visible ----
    asm volatile("griddepcontrol.wait;" ::: "memory");

    uint4 y0, y1, z0, z1;
    if (v1) {
        y0 = __ldg(&g_Y[sp.x]);
        z0 = __ldg(&g_Z[dp.x]);
        y1 = __ldg(&g_Y[sp.y]);
        z1 = __ldg(&g_Z[dp.y]);
    } else if (v0) {
        y0 = __ldg(&g_Y[sp.x]);
        z0 = __ldg(&g_Z[dp.x]);
        y1 = make_uint4(0, 0, 0, 0);
        z1 = make_uint4(0, 0, 0, 0);
    } else {
        y0 = y1 = z0 = z1 = make_uint4(0, 0, 0, 0);
    }

    float a[18];
    decode_edge_sum(y0, z0, a);
    decode_edge_sum(y1, z1, a + 9);

#pragma unroll
    for (int k = 0; k < 9; k++)
        sbuf[threadIdx.x * 9 + k] = tanh_h2(a[2 * k], a[2 * k + 1]);
    __syncthreads();

    // coalesced output: 2304 half2 per block -> float2 stores
    long long lim    = (long long)E * 9;               // total floats
    long long g2base = (long long)blockIdx.x * 2304;   // half2 index base
#pragma unroll
    for (int it = 0; it < 9; it++) {
        int i = it * 256 + threadIdx.x;                // 0..2303
        long long g2 = g2base + i;
        long long f0 = 2 * g2;
        if (f0 + 1 < lim) {
            union { unsigned int u; __half2 h; } cvt; cvt.u = sbuf[i];
            reinterpret_cast<float2*>(out)[g2] = __half22float2(cvt.h);
        } else if (f0 < lim) {
            union { unsigned int u; __half2 h; } cvt; cvt.u = sbuf[i];
            out[f0] = __low2float(cvt.h);
        }
    }
}

extern "C" void kernel_launch(void* const* d_in, const int* in_sizes, int n_in,
                              void* d_out, int out_size) {
    // metadata order: x [N,32] f32, edge_index [2,E] i32, node_types [N] i32, W [9,72] f32
    const float* x  = (const float*)d_in[0];
    const int*   ei = (const int*)d_in[1];
    const int*   nt = (const int*)d_in[2];
    const float* W  = (const float*)d_in[3];
    float* out = (float*)d_out;

    int N = in_sizes[2];
    int E = in_sizes[1] / 2;

    node_precompute<<<(N + 255) / 256, 256>>>(x, nt, W, N);

    // Edge kernel launched as a programmatic dependent of the precompute.
    cudaLaunchConfig_t cfg = {};
    cfg.gridDim  = dim3((E + EPB - 1) / EPB, 1, 1);
    cfg.blockDim = dim3(256, 1, 1);
    cfg.dynamicSmemBytes = 0;
    cudaLaunchAttribute attrs[1];
    attrs[0].id = cudaLaunchAttributeProgrammaticStreamSerialization;
    attrs[0].val.programmaticStreamSerializationAllowed = 1;
    cfg.attrs = attrs;
    cfg.numAttrs = 1;
    cudaLaunchKernelEx(&cfg, edge_kernel, ei, out, E);
}

// round 15
// speedup vs baseline: 1.4016x; 1.0984x over previous
#include <cuda_runtime.h>
#include <cuda_fp16.h>
#include <cstdint>

#define MAXN 131072
#define EPB 512   // edges per block (256 threads x 2)

// Packed tables: one uint4 (16B) per node per table.
// 12-bit unsigned q values (bias 2048) + fp16 row scale.
__device__ uint4 g_Y[MAXN];
__device__ uint4 g_Z[MAXN];

// ---------------- helpers ----------------
__device__ __forceinline__ unsigned long long packf2(float lo, float hi) {
    unsigned long long r;
    asm("mov.b64 %0, {%1, %2};" : "=l"(r) : "f"(lo), "f"(hi));
    return r;
}
__device__ __forceinline__ void unpackf2(unsigned long long v, float& lo, float& hi) {
    asm("mov.b64 {%0, %1}, %2;" : "=f"(lo), "=f"(hi) : "l"(v));
}
__device__ __forceinline__ void fma2(unsigned long long& acc,
                                     unsigned long long a, unsigned long long b) {
    asm("fma.rn.f32x2 %0, %1, %2, %0;" : "+l"(acc) : "l"(a), "l"(b));
}

__device__ __forceinline__ unsigned int tanh_h2(float lo, float hi) {
    __half2 h = __floats2half2_rn(lo, hi);
    unsigned int u;
    { union { __half2 h; unsigned int u; } cvt; cvt.h = h; u = cvt.u; }
    asm("tanh.approx.f16x2 %0, %0;" : "+r"(u));
    return u;
}

__device__ __forceinline__ uint4 pack_row(const float* v) {
    float mx = fabsf(v[0]);
#pragma unroll
    for (int o = 1; o < 9; o++) mx = fmaxf(mx, fabsf(v[o]));
    // quantize against the STORED (fp16-rounded) scale: no systematic scale error
    __half hs = __float2half_rn(fmaxf(mx, 1e-20f) * (1.0f / 2047.0f));
    float inv = __fdividef(1.0f, __half2float(hs));

    unsigned int q[9];
#pragma unroll
    for (int o = 0; o < 9; o++) {
        int qi = __float2int_rn(v[o] * inv);
        qi = max(-2047, min(2047, qi));
        q[o] = (unsigned int)(qi + 2048);
    }
    uint4 w;
    w.x = q[0] | (q[1] << 12) | (q[2] << 24);
    w.y = (q[2] >> 8) | (q[3] << 4) | (q[4] << 16) | (q[5] << 28);
    w.z = (q[5] >> 4) | (q[6] << 8) | (q[7] << 20);
    w.w = q[8] | ((unsigned int)__half_as_ushort(hs) << 16);
    return w;
}

__device__ __forceinline__ void unpack_row(uint4 w, float q[9], float& s) {
    q[0] = (float)( w.x        & 0xFFFu);
    q[1] = (float)((w.x >> 12) & 0xFFFu);
    q[2] = (float)(((w.x >> 24) | (w.y << 8)) & 0xFFFu);
    q[3] = (float)((w.y >> 4)  & 0xFFFu);
    q[4] = (float)((w.y >> 16) & 0xFFFu);
    q[5] = (float)(((w.y >> 28) | (w.z << 4)) & 0xFFFu);
    q[6] = (float)((w.z >> 8)  & 0xFFFu);
    q[7] = (float)( w.z >> 20);
    q[8] = (float)( w.w        & 0xFFFu);
    s = __half2float(__ushort_as_half((unsigned short)(w.w >> 16)));
}

__device__ __forceinline__ void decode_edge_sum(uint4 yw, uint4 zw, float* a) {
    float qy[9], qz[9], sy, sz;
    unpack_row(yw, qy, sy);
    unpack_row(zw, qz, sz);
    float c = -2048.0f * (sy + sz);
#pragma unroll
    for (int o = 0; o < 9; o++)
        a[o] = fmaf(sy, qy[o], fmaf(sz, qz[o], c));
}

// ---------------------------------------------------------------------------
// Kernel 1: per-node precompute with packed f32x2 FMAs (288 instr/node vs 576).
// Standalone kernel -> no register/occupancy constraint (391 blocks = 0.53
// waves; latency-bound, not slot-bound). x staged coalesced; interleaved
// (Y,Z) weight pairs in smem. PDL trigger at block start.
// ---------------------------------------------------------------------------
__global__ void __launch_bounds__(256)
node_precompute(const float* __restrict__ x,
                const int* __restrict__ node_types,
                const float* __restrict__ W,
                int N) {
    asm volatile("griddepcontrol.launch_dependents;" ::: "memory");

    // sWp[o*36+d]    = (W[o][d], W[o][32+d])        d in [0,32)
    // sWp[o*36+32+t] = (W[o][64+t], W[o][68+t])     t in [0,4)
    __shared__ __align__(16) float2 sWp[9 * 36];
    __shared__ __align__(16) float xs[256 * 36];

    for (int i = threadIdx.x; i < 9 * 36; i += 256) {
        int o = i / 36, d = i % 36;
        float a, b;
        if (d < 32) { a = W[o * 72 + d];             b = W[o * 72 + 32 + d]; }
        else        { a = W[o * 72 + 64 + (d - 32)]; b = W[o * 72 + 68 + (d - 32)]; }
        sWp[i] = make_float2(a, b);
    }

    int base = blockIdx.x * 256;
    const float4* xp = reinterpret_cast<const float4*>(x);
#pragma unroll
    for (int i = 0; i < 8; i++) {
        int lin = i * 256 + threadIdx.x;
        int nl  = lin >> 3;
        int cp  = lin & 7;
        if (base + nl < N)
            *reinterpret_cast<float4*>(xs + nl * 36 + cp * 4) =
                xp[(size_t)(base + nl) * 8 + cp];
    }
    __syncthreads();

    int n = base + threadIdx.x;
    if (n >= N) return;

    int t = node_types[n];

    unsigned long long acc[9];
#pragma unroll
    for (int o = 0; o < 9; o++)
        acc[o] = *reinterpret_cast<const unsigned long long*>(&sWp[o * 36 + 32 + t]);

    const float4* xrow = reinterpret_cast<const float4*>(xs + threadIdx.x * 36);
#pragma unroll
    for (int i = 0; i < 8; i++) {
        float4 xv = xrow[i];
        unsigned long long x0 = packf2(xv.x, xv.x);
        unsigned long long x1 = packf2(xv.y, xv.y);
        unsigned long long x2 = packf2(xv.z, xv.z);
        unsigned long long x3 = packf2(xv.w, xv.w);
#pragma unroll
        for (int o = 0; o < 9; o++) {
            const ulonglong2* wp =
                reinterpret_cast<const ulonglong2*>(&sWp[o * 36 + 4 * i]);
            ulonglong2 wa = wp[0];   // pairs for d=4i, 4i+1
            ulonglong2 wb = wp[1];   // pairs for d=4i+2, 4i+3
            fma2(acc[o], x0, wa.x);
            fma2(acc[o], x1, wa.y);
            fma2(acc[o], x2, wb.x);
            fma2(acc[o], x3, wb.y);
        }
    }

    float yv[9], zv[9];
#pragma unroll
    for (int o = 0; o < 9; o++) unpackf2(acc[o], yv[o], zv[o]);
    g_Y[n] = pack_row(yv);
    g_Z[n] = pack_row(zv);
}

// ---------------------------------------------------------------------------
// Kernel 2 (R7 body + PDL): ei loads BEFORE griddepcontrol.wait; 2 edges per
// thread; 4 scattered LDG.128; SIMD tanh; half2 staging; coalesced stores.
// ---------------------------------------------------------------------------
__global__ void __launch_bounds__(256)
edge_kernel(const int* __restrict__ ei,
            float* __restrict__ out,
            int E) {
    __shared__ unsigned int sbuf[EPB * 9 / 2];   // 2304 half2 = 9216 B

    int t  = blockIdx.x * 256 + threadIdx.x;   // pair index
    int e0 = 2 * t;
    bool v0 = (e0 < E), v1 = (e0 + 1 < E);

    // ---- prologue: table-independent index loads ----
    int2 sp = make_int2(0, 0), dp = make_int2(0, 0);
    if (v1) {
        if ((E & 1) == 0) {
            sp = reinterpret_cast<const int2*>(ei)[t];
            dp = reinterpret_cast<const int2*>(ei + E)[t];
        } else {
            sp = make_int2(ei[e0], ei[e0 + 1]);
            dp = make_int2(ei[E + e0], ei[E + e0 + 1]);
        }
    } else if (v0) {
        sp.x = ei[e0];
        dp.x = ei[E + e0];
    }

    // ---- wait for the precompute grid's memory to be visible ----
    asm volatile("griddepcontrol.wait;" ::: "memory");

    uint4 y0, y1, z0, z1;
    if (v1) {
        y0 = __ldg(&g_Y[sp.x]);
        z0 = __ldg(&g_Z[dp.x]);
        y1 = __ldg(&g_Y[sp.y]);
        z1 = __ldg(&g_Z[dp.y]);
    } else if (v0) {
        y0 = __ldg(&g_Y[sp.x]);
        z0 = __ldg(&g_Z[dp.x]);
        y1 = make_uint4(0, 0, 0, 0);
        z1 = make_uint4(0, 0, 0, 0);
    } else {
        y0 = y1 = z0 = z1 = make_uint4(0, 0, 0, 0);
    }

    float a[18];
    decode_edge_sum(y0, z0, a);
    decode_edge_sum(y1, z1, a + 9);

#pragma unroll
    for (int k = 0; k < 9; k++)
        sbuf[threadIdx.x * 9 + k] = tanh_h2(a[2 * k], a[2 * k + 1]);
    __syncthreads();

    // coalesced output: 2304 half2 per block -> float2 stores
    long long lim    = (long long)E * 9;               // total floats
    long long g2base = (long long)blockIdx.x * 2304;   // half2 index base
#pragma unroll
    for (int it = 0; it < 9; it++) {
        int i = it * 256 + threadIdx.x;                // 0..2303
        long long g2 = g2base + i;
        long long f0 = 2 * g2;
        if (f0 + 1 < lim) {
            union { unsigned int u; __half2 h; } cvt; cvt.u = sbuf[i];
            reinterpret_cast<float2*>(out)[g2] = __half22float2(cvt.h);
        } else if (f0 < lim) {
            union { unsigned int u; __half2 h; } cvt; cvt.u = sbuf[i];
            out[f0] = __low2float(cvt.h);
        }
    }
}

extern "C" void kernel_launch(void* const* d_in, const int* in_sizes, int n_in,
                              void* d_out, int out_size) {
    // metadata order: x [N,32] f32, edge_index [2,E] i32, node_types [N] i32, W [9,72] f32
    const float* x  = (const float*)d_in[0];
    const int*   ei = (const int*)d_in[1];
    const int*   nt = (const int*)d_in[2];
    const float* W  = (const float*)d_in[3];
    float* out = (float*)d_out;

    int N = in_sizes[2];
    int E = in_sizes[1] / 2;

    node_precompute<<<(N + 255) / 256, 256>>>(x, nt, W, N);

    // Edge kernel launched as a programmatic dependent of the precompute.
    cudaLaunchConfig_t cfg = {};
    cfg.gridDim  = dim3((E + EPB - 1) / EPB, 1, 1);
    cfg.blockDim = dim3(256, 1, 1);
    cfg.dynamicSmemBytes = 0;
    cudaLaunchAttribute attrs[1];
    attrs[0].id = cudaLaunchAttributeProgrammaticStreamSerialization;
    attrs[0].val.programmaticStreamSerializationAllowed = 1;
    cfg.attrs = attrs;
    cfg.numAttrs = 1;
    cudaLaunchKernelEx(&cfg, edge_kernel, ei, out, E);
}